// round 1
// baseline (speedup 1.0000x reference)
#include <cuda_runtime.h>
#include <cuda_bf16.h>
#include <math.h>

// ---------------- Model constants ----------------
#define DEPTH   12
#define DIM     768
#define HEADS   12
#define MLPD    3072
#define PP      16
#define GG      14
#define NCLS    1000
#define NTOK    197           // G*G + 1
#define HD      64
#define BATCH   32
#define SEQ     (BATCH * NTOK)        // 6304
#define PTOK    196
#define PM      (BATCH * PTOK)        // 6272

// ---------------- Scratch (device globals, no allocations) ----------------
__device__ float g_patches[PM * DIM];        // im2col output
__device__ float g_t     [SEQ * DIM];        // residual stream
__device__ float g_h     [SEQ * DIM];        // LN output
__device__ float g_qkv   [SEQ * 3 * DIM];    // qkv
__device__ float g_o     [SEQ * DIM];        // attention out / patch-embed tmp
__device__ float g_mlp   [SEQ * MLPD];       // MLP hidden

// ---------------- im2col ----------------
__global__ void im2col_kernel(const float* __restrict__ x, float* __restrict__ out) {
    int idx = blockIdx.x * blockDim.x + threadIdx.x;
    if (idx >= PM * DIM) return;
    int row = idx / DIM;       // b*196 + p
    int col = idx - row * DIM; // c*256 + p1*16 + p2
    int b  = row / PTOK;
    int pt = row - b * PTOK;
    int gi = pt / GG, gj = pt - gi * GG;
    int c  = col >> 8;
    int r  = col & 255;
    int p1 = r >> 4, p2 = r & 15;
    int xi = ((b * 3 + c) * 224 + gi * PP + p1) * 224 + (gj * PP + p2);
    out[idx] = x[xi];
}

// ---------------- assemble: cls token + pos embed ----------------
__global__ void assemble_kernel(const float* __restrict__ pe,
                                const float* __restrict__ cls,
                                const float* __restrict__ pos,
                                float* __restrict__ t) {
    int idx = blockIdx.x * blockDim.x + threadIdx.x;
    if (idx >= SEQ * DIM) return;
    int row = idx / DIM;
    int c   = idx - row * DIM;
    int b   = row / NTOK;
    int n   = row - b * NTOK;
    float v;
    if (n == 0) v = cls[c];
    else        v = pe[(size_t)(b * PTOK + n - 1) * DIM + c];
    t[idx] = v + pos[n * DIM + c];
}

// ---------------- GEMM: C = act(A@W + bias [+ res]) ----------------
// A: MxK row-major, W: KxN row-major, N % 128 == 0, K % 8 == 0.
// act: 0 = none, 1 = exact GELU.
__device__ __forceinline__ float gelu_exact(float x) {
    return 0.5f * x * (1.0f + erff(x * 0.70710678118654752f));
}

__global__ void __launch_bounds__(256)
gemm128(const float* __restrict__ A, const float* __restrict__ W,
        const float* __restrict__ bias, const float* __restrict__ res,
        float* __restrict__ C, int M, int Nd, int K, int act) {
    __shared__ float As[8][128];
    __shared__ float Bs[8][128];

    int tid = threadIdx.x;
    int bn0 = blockIdx.x * 128;
    int bm0 = blockIdx.y * 128;
    int tx = tid & 15, ty = tid >> 4;

    float acc[8][8];
#pragma unroll
    for (int i = 0; i < 8; i++)
#pragma unroll
        for (int j = 0; j < 8; j++) acc[i][j] = 0.0f;

    int arow = tid >> 1;
    int acol = (tid & 1) * 4;
    int brow = tid >> 5;
    int bcol = (tid & 31) * 4;
    int gm_a = bm0 + arow;

    for (int k0 = 0; k0 < K; k0 += 8) {
        float4 av;
        if (gm_a < M) av = *(const float4*)(A + (size_t)gm_a * K + k0 + acol);
        else          av = make_float4(0.f, 0.f, 0.f, 0.f);
        As[acol + 0][arow] = av.x;
        As[acol + 1][arow] = av.y;
        As[acol + 2][arow] = av.z;
        As[acol + 3][arow] = av.w;

        *(float4*)&Bs[brow][bcol] =
            *(const float4*)(W + (size_t)(k0 + brow) * Nd + bn0 + bcol);
        __syncthreads();

#pragma unroll
        for (int kk = 0; kk < 8; kk++) {
            float a[8], b[8];
            float4 a0 = *(const float4*)&As[kk][ty * 8];
            float4 a1 = *(const float4*)&As[kk][ty * 8 + 4];
            float4 b0 = *(const float4*)&Bs[kk][tx * 8];
            float4 b1 = *(const float4*)&Bs[kk][tx * 8 + 4];
            a[0]=a0.x;a[1]=a0.y;a[2]=a0.z;a[3]=a0.w;a[4]=a1.x;a[5]=a1.y;a[6]=a1.z;a[7]=a1.w;
            b[0]=b0.x;b[1]=b0.y;b[2]=b0.z;b[3]=b0.w;b[4]=b1.x;b[5]=b1.y;b[6]=b1.z;b[7]=b1.w;
#pragma unroll
            for (int i = 0; i < 8; i++)
#pragma unroll
                for (int j = 0; j < 8; j++)
                    acc[i][j] = fmaf(a[i], b[j], acc[i][j]);
        }
        __syncthreads();
    }

#pragma unroll
    for (int i = 0; i < 8; i++) {
        int gm = bm0 + ty * 8 + i;
        if (gm >= M) continue;
#pragma unroll
        for (int j = 0; j < 8; j++) {
            int gn = bn0 + tx * 8 + j;
            float v = acc[i][j] + bias[gn];
            if (res) v += res[(size_t)gm * Nd + gn];
            if (act == 1) v = gelu_exact(v);
            C[(size_t)gm * Nd + gn] = v;
        }
    }
}

// ---------------- LayerNorm (one block per row) ----------------
__global__ void __launch_bounds__(256)
ln_kernel(const float* __restrict__ in, const float* __restrict__ g,
          const float* __restrict__ b, float* __restrict__ out) {
    __shared__ float red[256];
    __shared__ float s_mean, s_rstd;
    int row = blockIdx.x;
    int tid = threadIdx.x;
    const float* x = in + (size_t)row * DIM;

    float v0 = x[tid], v1 = x[tid + 256], v2 = x[tid + 512];
    red[tid] = v0 + v1 + v2;
    __syncthreads();
    for (int s = 128; s > 0; s >>= 1) {
        if (tid < s) red[tid] += red[tid + s];
        __syncthreads();
    }
    if (tid == 0) s_mean = red[0] * (1.0f / DIM);
    __syncthreads();
    float m = s_mean;

    float d0 = v0 - m, d1 = v1 - m, d2 = v2 - m;
    red[tid] = d0 * d0 + d1 * d1 + d2 * d2;
    __syncthreads();
    for (int s = 128; s > 0; s >>= 1) {
        if (tid < s) red[tid] += red[tid + s];
        __syncthreads();
    }
    if (tid == 0) s_rstd = rsqrtf(red[0] * (1.0f / DIM) + 1e-6f);
    __syncthreads();
    float rs = s_rstd;

    float* y = out + (size_t)row * DIM;
    y[tid]       = d0 * rs * g[tid]       + b[tid];
    y[tid + 256] = d1 * rs * g[tid + 256] + b[tid + 256];
    y[tid + 512] = d2 * rs * g[tid + 512] + b[tid + 512];
}

// ---------------- Attention (one block per (b, head)) ----------------
// smem: K (197 rows, stride 65, padded to 12808) | V (197x64) | qbuf 8x64 | probs 8x200
#define KSTRIDE 65
#define SM_K    0
#define SM_V    12808
#define SM_Q    (SM_V + 197 * 64)         // 25416
#define SM_P    (SM_Q + 8 * 64)           // 25928
#define SM_ATTN_FLOATS (SM_P + 8 * 200)   // 27528
#define SM_ATTN_BYTES  (SM_ATTN_FLOATS * 4)

__global__ void __launch_bounds__(256)
attn_kernel(const float* __restrict__ qkv, const float* __restrict__ mask,
            float* __restrict__ o) {
    extern __shared__ float sm[];
    float* Ksm = sm + SM_K;
    float* Vsm = sm + SM_V;
    int h = blockIdx.x;
    int b = blockIdx.y;
    int tid = threadIdx.x;
    const float* base = qkv + (size_t)b * NTOK * (3 * DIM);

    // stage K and V for this head
    for (int i4 = tid; i4 < NTOK * 16; i4 += 256) {
        int n  = i4 >> 4;
        int d4 = (i4 & 15) << 2;
        const float* rowp = base + (size_t)n * (3 * DIM) + h * HD + d4;
        float4 kv = *(const float4*)(rowp + DIM);        // K slot
        Ksm[n * KSTRIDE + d4 + 0] = kv.x;
        Ksm[n * KSTRIDE + d4 + 1] = kv.y;
        Ksm[n * KSTRIDE + d4 + 2] = kv.z;
        Ksm[n * KSTRIDE + d4 + 3] = kv.w;
        *(float4*)&Vsm[n * 64 + d4] = *(const float4*)(rowp + 2 * DIM); // V slot
    }
    __syncthreads();

    int wid = tid >> 5, lane = tid & 31;
    float* q = sm + SM_Q + wid * 64;
    float* p = sm + SM_P + wid * 200;

    for (int qi = wid; qi < NTOK; qi += 8) {
        const float* qrow = base + (size_t)qi * (3 * DIM) + h * HD;
        q[lane]      = qrow[lane];
        q[lane + 32] = qrow[lane + 32];
        __syncwarp();

        float s[7];
        float mx = -1e30f;
#pragma unroll
        for (int t = 0; t < 7; t++) {
            int j = t * 32 + lane;
            if (j < NTOK) {
                float acc = 0.0f;
#pragma unroll
                for (int d = 0; d < HD; d++)
                    acc = fmaf(q[d], Ksm[j * KSTRIDE + d], acc);
                acc *= 0.125f;                 // HD^-0.5
                acc *= mask[qi * NTOK + j];
                s[t] = acc;
                mx = fmaxf(mx, acc);
            } else {
                s[t] = -1e30f;
            }
        }
#pragma unroll
        for (int off = 16; off > 0; off >>= 1)
            mx = fmaxf(mx, __shfl_xor_sync(0xffffffffu, mx, off));

        float sum = 0.0f;
#pragma unroll
        for (int t = 0; t < 7; t++) {
            s[t] = __expf(s[t] - mx);
            sum += s[t];
        }
#pragma unroll
        for (int off = 16; off > 0; off >>= 1)
            sum += __shfl_xor_sync(0xffffffffu, sum, off);
        float inv = 1.0f / sum;
#pragma unroll
        for (int t = 0; t < 7; t++) {
            int j = t * 32 + lane;
            if (j < NTOK) p[j] = s[t] * inv;
        }
        __syncwarp();

        // o = probs @ V
        float* op = o + (size_t)(b * NTOK + qi) * DIM + h * HD;
#pragma unroll
        for (int dd = 0; dd < 2; dd++) {
            int d = lane + dd * 32;
            float acc = 0.0f;
            for (int j = 0; j < NTOK; j++)
                acc = fmaf(p[j], Vsm[j * 64 + d], acc);
            op[d] = acc;
        }
        __syncwarp();
    }
}

// ---------------- Head: out[b,c] = pooled[b] . head_w[:,c] + head_b[c] ----------------
__global__ void __launch_bounds__(256)
head_kernel(const float* __restrict__ hf, const float* __restrict__ w,
            const float* __restrict__ hb, float* __restrict__ out) {
    __shared__ float pooled[DIM];
    int b = blockIdx.x;
    int tid = threadIdx.x;
    for (int i = tid; i < DIM; i += 256)
        pooled[i] = hf[(size_t)(b * NTOK) * DIM + i];
    __syncthreads();
    for (int c = tid; c < NCLS; c += 256) {
        float acc = hb[c];
        for (int d = 0; d < DIM; d++)
            acc = fmaf(pooled[d], w[(size_t)d * NCLS + c], acc);
        out[(size_t)b * NCLS + c] = acc;
    }
}

// ---------------- Launch ----------------
extern "C" void kernel_launch(void* const* d_in, const int* in_sizes, int n_in,
                              void* d_out, int out_size) {
    const float* x        = (const float*)d_in[0];
    const float* cp_mask  = (const float*)d_in[1];
    const float* patch_w  = (const float*)d_in[2];
    const float* patch_b  = (const float*)d_in[3];
    const float* cls_tok  = (const float*)d_in[4];
    const float* pos_emb  = (const float*)d_in[5];
    const float* ln1_g    = (const float*)d_in[6];
    const float* ln1_b    = (const float*)d_in[7];
    const float* qkv_w    = (const float*)d_in[8];
    const float* qkv_b    = (const float*)d_in[9];
    const float* proj_w   = (const float*)d_in[10];
    const float* proj_b   = (const float*)d_in[11];
    const float* ln2_g    = (const float*)d_in[12];
    const float* ln2_b    = (const float*)d_in[13];
    const float* fc1_w    = (const float*)d_in[14];
    const float* fc1_b    = (const float*)d_in[15];
    const float* fc2_w    = (const float*)d_in[16];
    const float* fc2_b    = (const float*)d_in[17];
    const float* normf_g  = (const float*)d_in[18];
    const float* normf_b  = (const float*)d_in[19];
    const float* head_w   = (const float*)d_in[20];
    const float* head_b   = (const float*)d_in[21];
    float* out = (float*)d_out;

    float *pat, *t, *h, *qkv, *o, *mlp;
    cudaGetSymbolAddress((void**)&pat, g_patches);
    cudaGetSymbolAddress((void**)&t,   g_t);
    cudaGetSymbolAddress((void**)&h,   g_h);
    cudaGetSymbolAddress((void**)&qkv, g_qkv);
    cudaGetSymbolAddress((void**)&o,   g_o);
    cudaGetSymbolAddress((void**)&mlp, g_mlp);

    cudaFuncSetAttribute(attn_kernel,
                         cudaFuncAttributeMaxDynamicSharedMemorySize,
                         SM_ATTN_BYTES);

    // 1) im2col
    {
        int total = PM * DIM;
        im2col_kernel<<<(total + 255) / 256, 256>>>(x, pat);
    }
    // 2) patch embed GEMM: (6272,768) @ (768,768) -> g_o
    {
        dim3 grid(DIM / 128, (PM + 127) / 128);
        gemm128<<<grid, 256>>>(pat, patch_w, patch_b, nullptr, o, PM, DIM, DIM, 0);
    }
    // 3) assemble cls + pos -> g_t
    {
        int total = SEQ * DIM;
        assemble_kernel<<<(total + 255) / 256, 256>>>(o, cls_tok, pos_emb, t);
    }

    for (int i = 0; i < DEPTH; i++) {
        // LN1
        ln_kernel<<<SEQ, 256>>>(t, ln1_g + i * DIM, ln1_b + i * DIM, h);
        // QKV GEMM: (6304,768) @ (768,2304)
        {
            dim3 grid((3 * DIM) / 128, (SEQ + 127) / 128);
            gemm128<<<grid, 256>>>(h, qkv_w + (size_t)i * DIM * 3 * DIM,
                                   qkv_b + i * 3 * DIM, nullptr, qkv,
                                   SEQ, 3 * DIM, DIM, 0);
        }
        // Attention
        {
            dim3 grid(HEADS, BATCH);
            attn_kernel<<<grid, 256, SM_ATTN_BYTES>>>(qkv, cp_mask, o);
        }
        // Proj GEMM + residual: t = t + o @ proj_w + proj_b
        {
            dim3 grid(DIM / 128, (SEQ + 127) / 128);
            gemm128<<<grid, 256>>>(o, proj_w + (size_t)i * DIM * DIM,
                                   proj_b + i * DIM, t, t, SEQ, DIM, DIM, 0);
        }
        // LN2
        ln_kernel<<<SEQ, 256>>>(t, ln2_g + i * DIM, ln2_b + i * DIM, h);
        // FC1 + GELU: (6304,768) @ (768,3072)
        {
            dim3 grid(MLPD / 128, (SEQ + 127) / 128);
            gemm128<<<grid, 256>>>(h, fc1_w + (size_t)i * DIM * MLPD,
                                   fc1_b + i * MLPD, nullptr, mlp,
                                   SEQ, MLPD, DIM, 1);
        }
        // FC2 + residual: t = t + mlp @ fc2_w + fc2_b
        {
            dim3 grid(DIM / 128, (SEQ + 127) / 128);
            gemm128<<<grid, 256>>>(mlp, fc2_w + (size_t)i * MLPD * DIM,
                                   fc2_b + i * DIM, t, t, SEQ, DIM, MLPD, 0);
        }
    }

    // Final LN
    ln_kernel<<<SEQ, 256>>>(t, normf_g, normf_b, h);
    // Head
    head_kernel<<<BATCH, 256>>>(h, head_w, head_b, out);
}